// round 2
// baseline (speedup 1.0000x reference)
#include <cuda_runtime.h>

#define BATCH 8192
#define DIM   512
#define BM    64
#define BN    64
#define BK    32
#define MARGIN_F 0.3f

// Scratch (no allocations allowed in kernel_launch)
__device__ float g_sqn[BATCH];
__device__ int   g_lab[BATCH];
__device__ float g_sum;
__device__ int   g_cnt;

// ---------------------------------------------------------------------------
// Prep: squared norms per row (one warp per row), copy labels (int32!),
// zero accumulators.
// ---------------------------------------------------------------------------
__global__ void prep_kernel(const float* __restrict__ x,
                            const int* __restrict__ lab) {
    int row  = blockIdx.x * (blockDim.x >> 5) + (threadIdx.x >> 5);
    int lane = threadIdx.x & 31;
    if (row >= BATCH) return;
    const float4* xr = reinterpret_cast<const float4*>(x + (size_t)row * DIM);
    float s = 0.f;
    #pragma unroll
    for (int c = lane; c < DIM / 4; c += 32) {
        float4 v = xr[c];
        s += v.x * v.x + v.y * v.y + v.z * v.z + v.w * v.w;
    }
    #pragma unroll
    for (int o = 16; o; o >>= 1) s += __shfl_xor_sync(0xffffffffu, s, o);
    if (lane == 0) {
        g_sqn[row] = s;
        g_lab[row] = lab[row];
        if (row == 0) { g_sum = 0.f; g_cnt = 0; }
    }
}

// ---------------------------------------------------------------------------
// Main: fused SGEMM (X @ X^T) + hard-mining epilogue.
// Each block owns BM=64 rows i, streams all j in BN=64 tiles.
// 256 threads, 4x4 microtile each. Running hp2/hn2 (squared-distance space)
// kept in registers across the whole j loop; reduced across the 16 threads
// sharing a row at the end via intra-warp shuffles.
// ---------------------------------------------------------------------------
__global__ void __launch_bounds__(256, 1)
triplet_main(const float* __restrict__ x) {
    __shared__ float As[BK][BM];
    __shared__ float Bs[BK][BN];
    __shared__ float sqnB[BN];
    __shared__ int   labB[BN];

    const int i0  = blockIdx.x * BM;
    const int tid = threadIdx.x;
    const int tx  = tid & 15;   // column group (16 groups of 4 cols)
    const int ty  = tid >> 4;   // row group    (16 groups of 4 rows)

    float hp2[4], hn2[4];
    int   li[4];
    float sqi[4];
    #pragma unroll
    for (int ii = 0; ii < 4; ii++) {
        hp2[ii] = -1.f;            // marker: no positive found (d2 >= 0 always)
        hn2[ii] = 3.4e38f;         // marker: no negative found
        int i   = i0 + ty * 4 + ii;
        li[ii]  = g_lab[i];
        sqi[ii] = g_sqn[i];
    }

    for (int j0 = 0; j0 < BATCH; j0 += BN) {
        __syncthreads();  // previous epilogue readers done with sqnB/labB
        if (tid < BN) {
            sqnB[tid] = g_sqn[j0 + tid];
            labB[tid] = g_lab[j0 + tid];
        }

        float acc[4][4];
        #pragma unroll
        for (int ii = 0; ii < 4; ii++)
            #pragma unroll
            for (int jj = 0; jj < 4; jj++) acc[ii][jj] = 0.f;

        for (int k0 = 0; k0 < DIM; k0 += BK) {
            __syncthreads();  // previous k-step FMA reads done
            // Load A tile (64 x 32) and B tile (64 x 32), transposed into
            // smem as [k][row] for vectorized microtile reads.
            int t = tid;
            #pragma unroll
            for (int rep = 0; rep < 2; rep++, t += 256) {
                int r = t >> 3;
                int c = (t & 7) * 4;
                float4 v = *reinterpret_cast<const float4*>(
                    x + (size_t)(i0 + r) * DIM + k0 + c);
                As[c + 0][r] = v.x; As[c + 1][r] = v.y;
                As[c + 2][r] = v.z; As[c + 3][r] = v.w;
            }
            t = tid;
            #pragma unroll
            for (int rep = 0; rep < 2; rep++, t += 256) {
                int r = t >> 3;
                int c = (t & 7) * 4;
                float4 v = *reinterpret_cast<const float4*>(
                    x + (size_t)(j0 + r) * DIM + k0 + c);
                Bs[c + 0][r] = v.x; Bs[c + 1][r] = v.y;
                Bs[c + 2][r] = v.z; Bs[c + 3][r] = v.w;
            }
            __syncthreads();

            #pragma unroll
            for (int k = 0; k < BK; k++) {
                float a[4], b[4];
                *reinterpret_cast<float4*>(a) =
                    *reinterpret_cast<const float4*>(&As[k][ty * 4]);
                *reinterpret_cast<float4*>(b) =
                    *reinterpret_cast<const float4*>(&Bs[k][tx * 4]);
                #pragma unroll
                for (int ii = 0; ii < 4; ii++)
                    #pragma unroll
                    for (int jj = 0; jj < 4; jj++)
                        acc[ii][jj] = fmaf(a[ii], b[jj], acc[ii][jj]);
            }
        }

        // Epilogue for this j tile: update running hard-pos / hard-neg in d2.
        #pragma unroll
        for (int jj = 0; jj < 4; jj++) {
            int   jl  = tx * 4 + jj;
            int   j   = j0 + jl;
            float sqj = sqnB[jl];
            int   lj  = labB[jl];
            #pragma unroll
            for (int ii = 0; ii < 4; ii++) {
                float d2 = fmaxf(fmaf(-2.f, acc[ii][jj], sqi[ii] + sqj), 0.f);
                int   i  = i0 + ty * 4 + ii;
                if (lj == li[ii]) {
                    if (j != i) hp2[ii] = fmaxf(hp2[ii], d2);
                } else {
                    hn2[ii] = fminf(hn2[ii], d2);
                }
            }
        }
    }

    // Reduce across the 16 threads (same ty, tx=0..15) sharing each row.
    // These are contiguous 16-lane groups within a warp -> xor shuffles.
    float lsum = 0.f;
    int   lcnt = 0;
    #pragma unroll
    for (int ii = 0; ii < 4; ii++) {
        float hp = hp2[ii], hn = hn2[ii];
        #pragma unroll
        for (int off = 8; off; off >>= 1) {
            hp = fmaxf(hp, __shfl_xor_sync(0xffffffffu, hp, off));
            hn = fminf(hn, __shfl_xor_sync(0xffffffffu, hn, off));
        }
        if (tx == 0) {
            bool valid = (hp >= 0.f) && (hn < 3.0e38f);
            if (valid) {
                float per = sqrtf(hp + 1e-16f) - sqrtf(hn + 1e-16f) + MARGIN_F;
                lsum += fmaxf(per, 0.f);
                lcnt += 1;
            }
        }
    }
    if (tx == 0) {
        atomicAdd(&g_sum, lsum);
        atomicAdd(&g_cnt, lcnt);
    }
}

__global__ void finalize_kernel(float* __restrict__ out) {
    out[0] = g_sum / fmaxf((float)g_cnt, 1.f);
}

extern "C" void kernel_launch(void* const* d_in, const int* in_sizes, int n_in,
                              void* d_out, int out_size) {
    const float* x   = (const float*)d_in[0];
    const int*   lab = (const int*)d_in[1];   // JAX x64-disabled: int32 labels
    float*       out = (float*)d_out;

    // 8 warps per block -> 1024 blocks cover 8192 rows
    prep_kernel<<<BATCH / 8, 256>>>(x, lab);
    triplet_main<<<BATCH / BM, 256>>>(x);
    finalize_kernel<<<1, 1>>>(out);
}

// round 4
// speedup vs baseline: 6.2394x; 6.2394x over previous
#include <cuda_runtime.h>
#include <cstdint>

#define BATCH    8192
#define DIM      512
#define MARGIN_F 0.3f

#define BM 128            // i rows per block
#define BN 256            // j cols per tile
#define BK 32             // k per chunk
#define NJHALF 4096
#define NJT (NJHALF / BN)         // 16 j-tiles
#define NKC (DIM / BK)            // 16 k-chunks
#define NCH (NJT * NKC)           // 256 chunks per block

// smem layout in u32 units
#define ASTRIDE 36
#define A_STAGE (BM * ASTRIDE)        // 4608
#define B_STAGE (BN * ASTRIDE)        // 9216
#define OFF_SQN 0
#define OFF_LAB 4096
#define OFF_A   8192
#define OFF_B   (OFF_A + 2 * A_STAGE) // 17408
#define SMEM_U32 (OFF_B + 2 * B_STAGE) // 35840
#define SMEM_BYTES (SMEM_U32 * 4)      // 143360

// device scratch
__device__ uint32_t g_xt[BATCH * DIM];   // tf32-rounded embeddings (b32)
__device__ float    g_sqn[BATCH];
__device__ int      g_lab[BATCH];
__device__ int      g_hp2[BATCH];        // float bits (d2 >= 0 -> int-monotone)
__device__ int      g_hn2[BATCH];

__device__ __forceinline__ uint32_t smem_addr(const void* p) {
    uint32_t a;
    asm("{ .reg .u64 t; cvta.to.shared.u64 t, %1; cvt.u32.u64 %0, t; }"
        : "=r"(a) : "l"(p));
    return a;
}
__device__ __forceinline__ void cp16(uint32_t saddr, const void* gptr) {
    asm volatile("cp.async.cg.shared.global [%0], [%1], 16;"
                 :: "r"(saddr), "l"(gptr) : "memory");
}
__device__ __forceinline__ void mma_tf32(float* c, const uint32_t* a,
                                         const uint32_t* b) {
    asm volatile(
        "mma.sync.aligned.m16n8k8.row.col.f32.tf32.tf32.f32 "
        "{%0,%1,%2,%3}, {%4,%5,%6,%7}, {%8,%9}, {%0,%1,%2,%3};"
        : "+f"(c[0]), "+f"(c[1]), "+f"(c[2]), "+f"(c[3])
        : "r"(a[0]), "r"(a[1]), "r"(a[2]), "r"(a[3]), "r"(b[0]), "r"(b[1]));
}

// ---------------------------------------------------------------------------
// Prep: tf32-round embeddings, squared norms (from original fp32), labels,
// init mining arrays. One warp per row.
// ---------------------------------------------------------------------------
__global__ void prep_kernel(const float* __restrict__ x,
                            const int* __restrict__ lab) {
    int row  = blockIdx.x * 8 + (threadIdx.x >> 5);
    int lane = threadIdx.x & 31;
    const float4* xr = reinterpret_cast<const float4*>(x + (size_t)row * DIM);
    float s = 0.f;
    #pragma unroll
    for (int it = 0; it < 4; it++) {
        int c = lane + it * 32;
        float4 v = xr[c];
        s += v.x * v.x + v.y * v.y + v.z * v.z + v.w * v.w;
        float vv[4] = {v.x, v.y, v.z, v.w};
        uint32_t tv[4];
        #pragma unroll
        for (int k = 0; k < 4; k++)
            asm("cvt.rna.tf32.f32 %0, %1;" : "=r"(tv[k]) : "f"(vv[k]));
        *reinterpret_cast<uint4*>(&g_xt[row * DIM + c * 4]) =
            make_uint4(tv[0], tv[1], tv[2], tv[3]);
    }
    #pragma unroll
    for (int o = 16; o; o >>= 1) s += __shfl_xor_sync(0xffffffffu, s, o);
    if (lane == 0) {
        g_sqn[row] = s;
        g_lab[row] = lab[row];
        g_hp2[row] = -1;           // sentinel: no positive
        g_hn2[row] = 0x7f800000;   // +inf: no negative
    }
}

// ---------------------------------------------------------------------------
// Main: tf32 mma.sync Gram + fused hard mining.
// Grid 128: block b -> i-block (b>>1)*128, j-half (b&1)*4096.
// 8 warps: warp tile 64x64, layout wr = wid&1 (row half), wc = wid>>1.
// ---------------------------------------------------------------------------
__global__ void __launch_bounds__(256, 1) triplet_mma() {
    extern __shared__ uint32_t su[];
    float* sqnH = reinterpret_cast<float*>(su + OFF_SQN);
    int*   labH = reinterpret_cast<int*>(su + OFF_LAB);

    const int tid  = threadIdx.x;
    const int wid  = tid >> 5;
    const int lane = tid & 31;
    const int wr   = wid & 1;        // 0/1: rows [0,64) / [64,128)
    const int wc   = wid >> 1;       // 0..3: cols 64*wc
    const int qrow = lane >> 2;      // 0..7
    const int qcol = lane & 3;       // 0..3

    const int i0    = (blockIdx.x >> 1) * BM;
    const int jbase = (blockIdx.x & 1) * NJHALF;

    // sqn/lab for this j-half into smem
    #pragma unroll
    for (int it = 0; it < NJHALF / 256; it++) {
        int j = tid + it * 256;
        sqnH[j] = g_sqn[jbase + j];
        labH[j] = g_lab[jbase + j];
    }

    // per-thread row metadata: rows = i0 + wr*64 + mf*16 + qrow + rh*8
    float sqi[4][2];
    int   li [4][2];
    #pragma unroll
    for (int mf = 0; mf < 4; mf++)
        #pragma unroll
        for (int rh = 0; rh < 2; rh++) {
            int r = i0 + wr * 64 + mf * 16 + qrow + rh * 8;
            sqi[mf][rh] = g_sqn[r];
            li [mf][rh] = g_lab[r];
        }

    float hp2[4][2], hn2[4][2];
    #pragma unroll
    for (int mf = 0; mf < 4; mf++)
        #pragma unroll
        for (int rh = 0; rh < 2; rh++) {
            hp2[mf][rh] = -1.0f;
            hn2[mf][rh] = __int_as_float(0x7f800000);
        }

    // chunk loader: chunk c -> j-tile c>>4, k-chunk c&15, stage c&1
    auto load_chunk = [&](int c) {
        const int jt = c >> 4, kc = c & 15, s = c & 1;
        const int j0 = jbase + jt * BN;
        const int k0 = kc * BK;
        uint32_t abase = smem_addr(su + OFF_A + s * A_STAGE);
        uint32_t bbase = smem_addr(su + OFF_B + s * B_STAGE);
        // A: 128 rows x 32 u32 = 1024 segs of 16B
        #pragma unroll
        for (int it = 0; it < 4; it++) {
            int seg = tid + it * 256;
            int m = seg >> 3, sc = seg & 7;
            cp16(abase + (m * ASTRIDE + sc * 4) * 4,
                 g_xt + (i0 + m) * DIM + k0 + sc * 4);
        }
        // B: 256 rows x 32 u32 = 2048 segs
        #pragma unroll
        for (int it = 0; it < 8; it++) {
            int seg = tid + it * 256;
            int n = seg >> 3, sc = seg & 7;
            cp16(bbase + (n * ASTRIDE + sc * 4) * 4,
                 g_xt + (j0 + n) * DIM + k0 + sc * 4);
        }
        asm volatile("cp.async.commit_group;" ::: "memory");
    };

    float acc[4][8][4];

    load_chunk(0);
    __syncthreads();   // also covers sqnH/labH visibility

    for (int c = 0; c < NCH; c++) {
        const int s  = c & 1;
        const int jt = c >> 4;
        const int kc = c & 15;

        if (c + 1 < NCH) {
            load_chunk(c + 1);
            asm volatile("cp.async.wait_group 1;" ::: "memory");
        } else {
            asm volatile("cp.async.wait_group 0;" ::: "memory");
        }
        __syncthreads();

        if (kc == 0) {
            #pragma unroll
            for (int mf = 0; mf < 4; mf++)
                #pragma unroll
                for (int nf = 0; nf < 8; nf++)
                    #pragma unroll
                    for (int q = 0; q < 4; q++) acc[mf][nf][q] = 0.f;
        }

        const uint32_t* A = su + OFF_A + s * A_STAGE;
        const uint32_t* B = su + OFF_B + s * B_STAGE;
        const int arow = wr * 64 + qrow;
        const int brow = wc * 64 + qrow;

        #pragma unroll
        for (int ks = 0; ks < 4; ks++) {
            const int kk = ks * 8 + qcol;
            uint32_t af[4][4], bf[8][2];
            #pragma unroll
            for (int mf = 0; mf < 4; mf++) {
                int r0 = (arow + mf * 16) * ASTRIDE;
                af[mf][0] = A[r0 + kk];
                af[mf][1] = A[r0 + 8 * ASTRIDE + kk];
                af[mf][2] = A[r0 + kk + 4];
                af[mf][3] = A[r0 + 8 * ASTRIDE + kk + 4];
            }
            #pragma unroll
            for (int nf = 0; nf < 8; nf++) {
                int n0 = (brow + nf * 8) * ASTRIDE;
                bf[nf][0] = B[n0 + kk];
                bf[nf][1] = B[n0 + kk + 4];
            }
            #pragma unroll
            for (int mf = 0; mf < 4; mf++)
                #pragma unroll
                for (int nf = 0; nf < 8; nf++)
                    mma_tf32(acc[mf][nf], af[mf], bf[nf]);
        }

        if (kc == 15) {
            // epilogue: mine this 128x256 dot tile
            const int j0 = jbase + jt * BN;
            #pragma unroll
            for (int nf = 0; nf < 8; nf++) {
                const int jl = wc * 64 + nf * 8 + qcol * 2;
                const int jloc = jt * BN + jl;
                float sqj0 = sqnH[jloc],     sqj1 = sqnH[jloc + 1];
                int   lj0  = labH[jloc],     lj1  = labH[jloc + 1];
                #pragma unroll
                for (int mf = 0; mf < 4; mf++)
                    #pragma unroll
                    for (int rh = 0; rh < 2; rh++) {
                        const int irow = i0 + wr * 64 + mf * 16 + qrow + rh * 8;
                        float d20 = fmaxf(fmaf(-2.f, acc[mf][nf][rh * 2 + 0],
                                               sqi[mf][rh] + sqj0), 0.f);
                        float d21 = fmaxf(fmaf(-2.f, acc[mf][nf][rh * 2 + 1],
                                               sqi[mf][rh] + sqj1), 0.f);
                        if (lj0 == li[mf][rh]) {
                            if (j0 + jl != irow)
                                hp2[mf][rh] = fmaxf(hp2[mf][rh], d20);
                        } else hn2[mf][rh] = fminf(hn2[mf][rh], d20);
                        if (lj1 == li[mf][rh]) {
                            if (j0 + jl + 1 != irow)
                                hp2[mf][rh] = fmaxf(hp2[mf][rh], d21);
                        } else hn2[mf][rh] = fminf(hn2[mf][rh], d21);
                    }
            }
        }
        __syncthreads();
    }

    // reduce across the 4 lanes of each quad (same rows, different cols)
    #pragma unroll
    for (int mf = 0; mf < 4; mf++)
        #pragma unroll
        for (int rh = 0; rh < 2; rh++) {
            float hp = hp2[mf][rh], hn = hn2[mf][rh];
            hp = fmaxf(hp, __shfl_xor_sync(0xffffffffu, hp, 1));
            hp = fmaxf(hp, __shfl_xor_sync(0xffffffffu, hp, 2));
            hn = fminf(hn, __shfl_xor_sync(0xffffffffu, hn, 1));
            hn = fminf(hn, __shfl_xor_sync(0xffffffffu, hn, 2));
            if (qcol == 0) {
                int r = i0 + wr * 64 + mf * 16 + qrow + rh * 8;
                atomicMax(&g_hp2[r], __float_as_int(hp));
                atomicMin(&g_hn2[r], __float_as_int(hn));
            }
        }
}

// ---------------------------------------------------------------------------
// Final reduce: per-row loss, masked mean.
// ---------------------------------------------------------------------------
__global__ void reduce_kernel(float* __restrict__ out) {
    __shared__ float ss[1024];
    __shared__ int   sc[1024];
    const int t = threadIdx.x;
    float lsum = 0.f; int lcnt = 0;
    for (int r = t; r < BATCH; r += 1024) {
        int hp = g_hp2[r], hn = g_hn2[r];
        if (hp >= 0 && hn < 0x7f800000) {
            float l = sqrtf(__int_as_float(hp) + 1e-16f)
                    - sqrtf(__int_as_float(hn) + 1e-16f) + MARGIN_F;
            lsum += fmaxf(l, 0.f);
            lcnt += 1;
        }
    }
    ss[t] = lsum; sc[t] = lcnt;
    __syncthreads();
    for (int o = 512; o; o >>= 1) {
        if (t < o) { ss[t] += ss[t + o]; sc[t] += sc[t + o]; }
        __syncthreads();
    }
    if (t == 0) out[0] = ss[0] / fmaxf((float)sc[0], 1.f);
}

extern "C" void kernel_launch(void* const* d_in, const int* in_sizes, int n_in,
                              void* d_out, int out_size) {
    const float* x   = (const float*)d_in[0];
    const int*   lab = (const int*)d_in[1];   // JAX x64-disabled: int32 labels
    float*       out = (float*)d_out;

    cudaFuncSetAttribute(triplet_mma,
                         cudaFuncAttributeMaxDynamicSharedMemorySize, SMEM_BYTES);

    prep_kernel<<<BATCH / 8, 256>>>(x, lab);
    triplet_mma<<<128, 256, SMEM_BYTES>>>();
    reduce_kernel<<<1, 1024>>>(out);
}

// round 5
// speedup vs baseline: 11.6825x; 1.8724x over previous
#include <cuda_runtime.h>
#include <cuda_fp16.h>
#include <cstdint>

#define BATCH    8192
#define DIM      512
#define MARGIN_F 0.3f

#define BM 128            // i rows per block
#define BN 256            // j cols per tile
#define BK 64             // k per chunk
#define NJHALF 4096
#define NJT (NJHALF / BN)         // 16 j-tiles
#define NKC (DIM / BK)            // 8 k-chunks
#define NCH (NJT * NKC)           // 128 chunks per block

// smem row stride: 64 halves data + 8 pad = 72 halves = 36 words (144B).
// bank start = 4*row mod 32 -> 8 rows x 4 words fully conflict-free.
#define RSTR_W  36                     // row stride in u32 words
#define A_STAGE_W (BM * RSTR_W)        // 4608 words
#define B_STAGE_W (BN * RSTR_W)        // 9216 words
#define OFF_SQN_B 0
#define OFF_LAB_B 16384
#define OFF_AB_B  32768
#define SMEM_BYTES (OFF_AB_B + 2 * (A_STAGE_W + B_STAGE_W) * 4)  // 143360

// device scratch
__device__ __half g_xh[BATCH * DIM];     // fp16 embeddings
__device__ float  g_sqn[BATCH];
__device__ int    g_lab[BATCH];
__device__ int    g_hp2[BATCH];          // float bits (d2 >= 0 -> int-monotone)
__device__ int    g_hn2[BATCH];

__device__ __forceinline__ uint32_t smem_addr(const void* p) {
    uint32_t a;
    asm("{ .reg .u64 t; cvta.to.shared.u64 t, %1; cvt.u32.u64 %0, t; }"
        : "=r"(a) : "l"(p));
    return a;
}
__device__ __forceinline__ void cp16(uint32_t saddr, const void* gptr) {
    asm volatile("cp.async.cg.shared.global [%0], [%1], 16;"
                 :: "r"(saddr), "l"(gptr) : "memory");
}
__device__ __forceinline__ void mma_fp16(float* c, const uint32_t* a,
                                         const uint32_t* b) {
    asm volatile(
        "mma.sync.aligned.m16n8k16.row.col.f32.f16.f16.f32 "
        "{%0,%1,%2,%3}, {%4,%5,%6,%7}, {%8,%9}, {%0,%1,%2,%3};"
        : "+f"(c[0]), "+f"(c[1]), "+f"(c[2]), "+f"(c[3])
        : "r"(a[0]), "r"(a[1]), "r"(a[2]), "r"(a[3]), "r"(b[0]), "r"(b[1]));
}

// ---------------------------------------------------------------------------
// Prep: fp16 conversion, fp32 squared norms, labels, mining-array init.
// One warp per row.
// ---------------------------------------------------------------------------
__global__ void prep_kernel(const float* __restrict__ x,
                            const int* __restrict__ lab) {
    int row  = blockIdx.x * 8 + (threadIdx.x >> 5);
    int lane = threadIdx.x & 31;
    const float4* xr = reinterpret_cast<const float4*>(x + (size_t)row * DIM);
    float s = 0.f;
    #pragma unroll
    for (int it = 0; it < 4; it++) {
        int c = lane + it * 32;
        float4 v = xr[c];
        s += v.x * v.x + v.y * v.y + v.z * v.z + v.w * v.w;
        __half2 h0 = __floats2half2_rn(v.x, v.y);
        __half2 h1 = __floats2half2_rn(v.z, v.w);
        *reinterpret_cast<__half2*>(&g_xh[row * DIM + c * 4])     = h0;
        *reinterpret_cast<__half2*>(&g_xh[row * DIM + c * 4 + 2]) = h1;
    }
    #pragma unroll
    for (int o = 16; o; o >>= 1) s += __shfl_xor_sync(0xffffffffu, s, o);
    if (lane == 0) {
        g_sqn[row] = s;
        g_lab[row] = lab[row];
        g_hp2[row] = -1;           // sentinel: no positive
        g_hn2[row] = 0x7f800000;   // +inf: no negative
    }
}

// ---------------------------------------------------------------------------
// Main: fp16 mma.sync (m16n8k16) Gram + fused hard mining.
// Grid 128: block b -> i-block (b>>1)*128, j-half (b&1)*4096.
// 8 warps: warp tile 64x64, wr = wid&1 (row half), wc = wid>>1 (col quarter).
// ---------------------------------------------------------------------------
__global__ void __launch_bounds__(256, 1) triplet_mma() {
    extern __shared__ char smem[];
    float*    sqnH = reinterpret_cast<float*>(smem + OFF_SQN_B);
    int*      labH = reinterpret_cast<int*>(smem + OFF_LAB_B);
    uint32_t* ab   = reinterpret_cast<uint32_t*>(smem + OFF_AB_B);

    const int tid  = threadIdx.x;
    const int wid  = tid >> 5;
    const int lane = tid & 31;
    const int wr   = wid & 1;        // 0/1: rows [0,64) / [64,128)
    const int wc   = wid >> 1;       // 0..3: cols 64*wc
    const int qrow = lane >> 2;      // 0..7
    const int qcol = lane & 3;       // 0..3

    const int i0    = (blockIdx.x >> 1) * BM;
    const int jbase = (blockIdx.x & 1) * NJHALF;

    // sqn/lab for this j-half into smem
    #pragma unroll
    for (int it = 0; it < NJHALF / 256; it++) {
        int j = tid + it * 256;
        sqnH[j] = g_sqn[jbase + j];
        labH[j] = g_lab[jbase + j];
    }

    // per-thread row metadata: rows = i0 + wr*64 + mf*16 + qrow + rh*8
    float sqi[4][2];
    int   li [4][2];
    #pragma unroll
    for (int mf = 0; mf < 4; mf++)
        #pragma unroll
        for (int rh = 0; rh < 2; rh++) {
            int r = i0 + wr * 64 + mf * 16 + qrow + rh * 8;
            sqi[mf][rh] = g_sqn[r];
            li [mf][rh] = g_lab[r];
        }

    float hp2[4][2], hn2[4][2];
    #pragma unroll
    for (int mf = 0; mf < 4; mf++)
        #pragma unroll
        for (int rh = 0; rh < 2; rh++) {
            hp2[mf][rh] = -1.0f;
            hn2[mf][rh] = __int_as_float(0x7f800000);
        }

    // chunk loader: chunk c -> j-tile c>>3, k-chunk c&7, stage c&1
    auto load_chunk = [&](int c) {
        const int jt = c >> 3, kc = c & 7, s = c & 1;
        const int j0 = jbase + jt * BN;
        const int k0 = kc * BK;
        uint32_t abase = smem_addr(ab + s * A_STAGE_W);
        uint32_t bbase = smem_addr(ab + 2 * A_STAGE_W + s * B_STAGE_W);
        // A: 128 rows x 8 segs of 16B = 1024 segs
        #pragma unroll
        for (int it = 0; it < 4; it++) {
            int seg = tid + it * 256;
            int m = seg >> 3, sc = seg & 7;
            cp16(abase + (m * RSTR_W + sc * 4) * 4,
                 g_xh + (i0 + m) * DIM + k0 + sc * 8);
        }
        // B: 256 rows x 8 segs = 2048 segs
        #pragma unroll
        for (int it = 0; it < 8; it++) {
            int seg = tid + it * 256;
            int n = seg >> 3, sc = seg & 7;
            cp16(bbase + (n * RSTR_W + sc * 4) * 4,
                 g_xh + (j0 + n) * DIM + k0 + sc * 8);
        }
        asm volatile("cp.async.commit_group;" ::: "memory");
    };

    float acc[4][8][4];

    load_chunk(0);
    __syncthreads();   // also covers sqnH/labH visibility

    for (int c = 0; c < NCH; c++) {
        const int s  = c & 1;
        const int jt = c >> 3;
        const int kc = c & 7;

        if (c + 1 < NCH) {
            load_chunk(c + 1);
            asm volatile("cp.async.wait_group 1;" ::: "memory");
        } else {
            asm volatile("cp.async.wait_group 0;" ::: "memory");
        }
        __syncthreads();

        if (kc == 0) {
            #pragma unroll
            for (int mf = 0; mf < 4; mf++)
                #pragma unroll
                for (int nf = 0; nf < 8; nf++)
                    #pragma unroll
                    for (int q = 0; q < 4; q++) acc[mf][nf][q] = 0.f;
        }

        const uint32_t* A = ab + s * A_STAGE_W;
        const uint32_t* B = ab + 2 * A_STAGE_W + s * B_STAGE_W;
        const int arow = wr * 64 + qrow;
        const int brow = wc * 64 + qrow;

        #pragma unroll
        for (int ks = 0; ks < 4; ks++) {               // 4 x k16 = BK 64
            const int kw = ks * 8 + qcol;              // word offset in row
            uint32_t af[4][4], bf[8][2];
            #pragma unroll
            for (int mf = 0; mf < 4; mf++) {
                int r0 = (arow + mf * 16) * RSTR_W;
                af[mf][0] = A[r0 + kw];
                af[mf][1] = A[r0 + 8 * RSTR_W + kw];
                af[mf][2] = A[r0 + kw + 4];
                af[mf][3] = A[r0 + 8 * RSTR_W + kw + 4];
            }
            #pragma unroll
            for (int nf = 0; nf < 8; nf++) {
                int n0 = (brow + nf * 8) * RSTR_W;
                bf[nf][0] = B[n0 + kw];
                bf[nf][1] = B[n0 + kw + 4];
            }
            #pragma unroll
            for (int mf = 0; mf < 4; mf++)
                #pragma unroll
                for (int nf = 0; nf < 8; nf++)
                    mma_fp16(acc[mf][nf], af[mf], bf[nf]);
        }

        if (kc == NKC - 1) {
            // epilogue: mine this 128x256 dot tile
            const int j0 = jbase + jt * BN;
            #pragma unroll
            for (int nf = 0; nf < 8; nf++) {
                const int jl = wc * 64 + nf * 8 + qcol * 2;
                const int jloc = jt * BN + jl;
                float sqj0 = sqnH[jloc],     sqj1 = sqnH[jloc + 1];
                int   lj0  = labH[jloc],     lj1  = labH[jloc + 1];
                #pragma unroll
                for (int mf = 0; mf < 4; mf++)
                    #pragma unroll
                    for (int rh = 0; rh < 2; rh++) {
                        const int irow = i0 + wr * 64 + mf * 16 + qrow + rh * 8;
                        float d20 = fmaxf(fmaf(-2.f, acc[mf][nf][rh * 2 + 0],
                                               sqi[mf][rh] + sqj0), 0.f);
                        float d21 = fmaxf(fmaf(-2.f, acc[mf][nf][rh * 2 + 1],
                                               sqi[mf][rh] + sqj1), 0.f);
                        if (lj0 == li[mf][rh]) {
                            if (j0 + jl != irow)
                                hp2[mf][rh] = fmaxf(hp2[mf][rh], d20);
                        } else hn2[mf][rh] = fminf(hn2[mf][rh], d20);
                        if (lj1 == li[mf][rh]) {
                            if (j0 + jl + 1 != irow)
                                hp2[mf][rh] = fmaxf(hp2[mf][rh], d21);
                        } else hn2[mf][rh] = fminf(hn2[mf][rh], d21);
                    }
            }
        }
        __syncthreads();
    }

    // reduce across the 4 lanes of each quad (same rows, different cols)
    #pragma unroll
    for (int mf = 0; mf < 4; mf++)
        #pragma unroll
        for (int rh = 0; rh < 2; rh++) {
            float hp = hp2[mf][rh], hn = hn2[mf][rh];
            hp = fmaxf(hp, __shfl_xor_sync(0xffffffffu, hp, 1));
            hp = fmaxf(hp, __shfl_xor_sync(0xffffffffu, hp, 2));
            hn = fminf(hn, __shfl_xor_sync(0xffffffffu, hn, 1));
            hn = fminf(hn, __shfl_xor_sync(0xffffffffu, hn, 2));
            if (qcol == 0) {
                int r = i0 + wr * 64 + mf * 16 + qrow + rh * 8;
                atomicMax(&g_hp2[r], __float_as_int(hp));
                atomicMin(&g_hn2[r], __float_as_int(hn));
            }
        }
}

// ---------------------------------------------------------------------------
// Final reduce: per-row loss, masked mean.
// ---------------------------------------------------------------------------
__global__ void reduce_kernel(float* __restrict__ out) {
    __shared__ float ss[1024];
    __shared__ int   sc[1024];
    const int t = threadIdx.x;
    float lsum = 0.f; int lcnt = 0;
    for (int r = t; r < BATCH; r += 1024) {
        int hp = g_hp2[r], hn = g_hn2[r];
        if (hp >= 0 && hn < 0x7f800000) {
            float l = sqrtf(__int_as_float(hp) + 1e-16f)
                    - sqrtf(__int_as_float(hn) + 1e-16f) + MARGIN_F;
            lsum += fmaxf(l, 0.f);
            lcnt += 1;
        }
    }
    ss[t] = lsum; sc[t] = lcnt;
    __syncthreads();
    for (int o = 512; o; o >>= 1) {
        if (t < o) { ss[t] += ss[t + o]; sc[t] += sc[t + o]; }
        __syncthreads();
    }
    if (t == 0) out[0] = ss[0] / fmaxf((float)sc[0], 1.f);
}

extern "C" void kernel_launch(void* const* d_in, const int* in_sizes, int n_in,
                              void* d_out, int out_size) {
    const float* x   = (const float*)d_in[0];
    const int*   lab = (const int*)d_in[1];   // JAX x64-disabled: int32 labels
    float*       out = (float*)d_out;

    cudaFuncSetAttribute(triplet_mma,
                         cudaFuncAttributeMaxDynamicSharedMemorySize, SMEM_BYTES);

    prep_kernel<<<BATCH / 8, 256>>>(x, lab);
    triplet_mma<<<128, 256, SMEM_BYTES>>>();
    reduce_kernel<<<1, 1024>>>(out);
}

// round 6
// speedup vs baseline: 12.1467x; 1.0397x over previous
#include <cuda_runtime.h>
#include <cuda_fp16.h>
#include <cstdint>

#define BATCH    8192
#define DIM      512
#define MARGIN_F 0.3f

#define BM 128            // i rows per block (A resident)
#define BN 256            // j cols per tile
#define BK 64             // k per B chunk
#define NJHALF 4096
#define NJT (NJHALF / BN)         // 16 j-tiles
#define NKC (DIM / BK)            // 8 k-chunks
#define NCH (NJT * NKC)           // 128 chunks per block

// A: resident 128 rows x 512 halves (+8 pad) = 260 words/row.
// B: staged   256 rows x 64 halves (+8 pad)  = 36 words/row.
// bank start = 4*row mod 32 in both -> ldmatrix conflict-free.
#define ASTR_W 260
#define BSTR_W 36
#define A_BYTES (BM * ASTR_W * 4)            // 133120
#define B_STAGE_BYTES (BN * BSTR_W * 4)      // 36864
#define OFF_SQNT 0
#define OFF_LABT 1024
#define OFF_A    2048
#define OFF_B    (OFF_A + A_BYTES)           // 135168
#define SMEM_BYTES (OFF_B + 2 * B_STAGE_BYTES)  // 208896

// device scratch
__device__ __half g_xh[BATCH * DIM];     // fp16 embeddings
__device__ float  g_sqn[BATCH];
__device__ int    g_lab[BATCH];
__device__ int    g_hp2[BATCH];          // float bits (d2 >= 0 -> int-monotone)
__device__ int    g_hn2[BATCH];

__device__ __forceinline__ uint32_t smem_u32(const void* p) {
    uint32_t a;
    asm("{ .reg .u64 t; cvta.to.shared.u64 t, %1; cvt.u32.u64 %0, t; }"
        : "=r"(a) : "l"(p));
    return a;
}
__device__ __forceinline__ void cp16(uint32_t saddr, const void* gptr) {
    asm volatile("cp.async.cg.shared.global [%0], [%1], 16;"
                 :: "r"(saddr), "l"(gptr) : "memory");
}
__device__ __forceinline__ void ldsm4(uint32_t* r, uint32_t addr) {
    asm volatile("ldmatrix.sync.aligned.m8n8.x4.shared.b16 {%0,%1,%2,%3}, [%4];"
                 : "=r"(r[0]), "=r"(r[1]), "=r"(r[2]), "=r"(r[3]) : "r"(addr));
}
__device__ __forceinline__ void mma_fp16(float* c, const uint32_t* a,
                                         const uint32_t* b) {
    asm volatile(
        "mma.sync.aligned.m16n8k16.row.col.f32.f16.f16.f32 "
        "{%0,%1,%2,%3}, {%4,%5,%6,%7}, {%8,%9}, {%0,%1,%2,%3};"
        : "+f"(c[0]), "+f"(c[1]), "+f"(c[2]), "+f"(c[3])
        : "r"(a[0]), "r"(a[1]), "r"(a[2]), "r"(a[3]), "r"(b[0]), "r"(b[1]));
}

// ---------------------------------------------------------------------------
// Prep: fp16 conversion, fp32 squared norms, labels, mining-array init.
// ---------------------------------------------------------------------------
__global__ void prep_kernel(const float* __restrict__ x,
                            const int* __restrict__ lab) {
    int row  = blockIdx.x * 8 + (threadIdx.x >> 5);
    int lane = threadIdx.x & 31;
    const float4* xr = reinterpret_cast<const float4*>(x + (size_t)row * DIM);
    float s = 0.f;
    #pragma unroll
    for (int it = 0; it < 4; it++) {
        int c = lane + it * 32;
        float4 v = xr[c];
        s += v.x * v.x + v.y * v.y + v.z * v.z + v.w * v.w;
        __half2 h0 = __floats2half2_rn(v.x, v.y);
        __half2 h1 = __floats2half2_rn(v.z, v.w);
        *reinterpret_cast<__half2*>(&g_xh[row * DIM + c * 4])     = h0;
        *reinterpret_cast<__half2*>(&g_xh[row * DIM + c * 4 + 2]) = h1;
    }
    #pragma unroll
    for (int o = 16; o; o >>= 1) s += __shfl_xor_sync(0xffffffffu, s, o);
    if (lane == 0) {
        g_sqn[row] = s;
        g_lab[row] = lab[row];
        g_hp2[row] = -1;           // sentinel: no positive
        g_hn2[row] = 0x7f800000;   // +inf: no negative
    }
}

// ---------------------------------------------------------------------------
// Main: fp16 mma.sync Gram + fused hard mining. A resident, ldmatrix frags.
// Grid 128: block b -> i-block (b>>1)*128, j-half (b&1)*4096.
// ---------------------------------------------------------------------------
__global__ void __launch_bounds__(256, 1) triplet_mma() {
    extern __shared__ char smem[];
    float* sqnT = reinterpret_cast<float*>(smem + OFF_SQNT);   // 256 entries
    int*   labT = reinterpret_cast<int*>(smem + OFF_LABT);

    const uint32_t sA = smem_u32(smem + OFF_A);
    const uint32_t sB = smem_u32(smem + OFF_B);

    const int tid  = threadIdx.x;
    const int lane = tid & 31;
    const int wid  = tid >> 5;
    const int wr   = wid & 1;        // row half
    const int wc   = wid >> 1;       // col quarter
    const int qrow = lane >> 2;
    const int qcol = lane & 3;

    const int i0    = (blockIdx.x >> 1) * BM;
    const int jbase = (blockIdx.x & 1) * NJHALF;

    // ldmatrix lane address bases (row = lane&15, k-half-sel = lane>>4)
    const int lrow = lane & 15, lksel = lane >> 4;
    uint32_t aAddr[4], bAddr[4];
    #pragma unroll
    for (int mf = 0; mf < 4; mf++)
        aAddr[mf] = sA + ((wr * 64 + mf * 16 + lrow) * ASTR_W + 4 * lksel) * 4;
    #pragma unroll
    for (int f = 0; f < 4; f++)
        bAddr[f] = sB + ((wc * 64 + f * 16 + lrow) * BSTR_W + 4 * lksel) * 4;

    // per-thread row metadata
    float sqi[4][2];
    int   li [4][2];
    #pragma unroll
    for (int mf = 0; mf < 4; mf++)
        #pragma unroll
        for (int rh = 0; rh < 2; rh++) {
            int r = i0 + wr * 64 + mf * 16 + qrow + rh * 8;
            sqi[mf][rh] = g_sqn[r];
            li [mf][rh] = g_lab[r];
        }

    float hp2[4][2], hn2[4][2];
    #pragma unroll
    for (int mf = 0; mf < 4; mf++)
        #pragma unroll
        for (int rh = 0; rh < 2; rh++) {
            hp2[mf][rh] = -1.0f;
            hn2[mf][rh] = __int_as_float(0x7f800000);
        }

    // ---- load resident A: 128 rows x 64 segs(16B) = 8192 segs ----
    #pragma unroll
    for (int it = 0; it < 32; it++) {
        int seg = tid + it * 256;
        int m = seg >> 6, sc = seg & 63;
        cp16(sA + (m * ASTR_W + sc * 4) * 4, g_xh + (i0 + m) * DIM + sc * 8);
    }

    // B chunk loader: chunk c -> j-tile c>>3, k-chunk c&7, stage c&1
    auto load_B = [&](int c) {
        const int jt = c >> 3, kc = c & 7, s = c & 1;
        const int j0 = jbase + jt * BN;
        const int k0 = kc * BK;
        const uint32_t bbase = sB + s * B_STAGE_BYTES;
        #pragma unroll
        for (int it = 0; it < 8; it++) {
            int seg = tid + it * 256;
            int n = seg >> 3, sc = seg & 7;
            cp16(bbase + (n * BSTR_W + sc * 4) * 4,
                 g_xh + (j0 + n) * DIM + k0 + sc * 8);
        }
        asm volatile("cp.async.commit_group;" ::: "memory");
    };

    load_B(0);   // group 0 = A + B0
    float acc[4][8][4];

    for (int c = 0; c < NCH; c++) {
        const int s  = c & 1;
        const int jt = c >> 3;
        const int kc = c & 7;
        const int j0 = jbase + jt * BN;

        if (c + 1 < NCH) {
            load_B(c + 1);
            asm volatile("cp.async.wait_group 1;" ::: "memory");
        } else {
            asm volatile("cp.async.wait_group 0;" ::: "memory");
        }
        if (kc == 0) {
            // stage this j-tile's sqn/lab (read at kc==7; syncs in between)
            sqnT[tid] = g_sqn[j0 + tid];
            labT[tid] = g_lab[j0 + tid];
            if (tid < BN - 256) { /* BN==256: nothing */ }
        }
        __syncthreads();

        if (kc == 0) {
            #pragma unroll
            for (int mf = 0; mf < 4; mf++)
                #pragma unroll
                for (int nf = 0; nf < 8; nf++)
                    #pragma unroll
                    for (int q = 0; q < 4; q++) acc[mf][nf][q] = 0.f;
        }

        const uint32_t aOff = (uint32_t)kc * 128u;   // kc*32 words * 4B
        const uint32_t bOff = (uint32_t)s * B_STAGE_BYTES;

        #pragma unroll
        for (int ks = 0; ks < 4; ks++) {             // 4 x k16 = BK 64
            const uint32_t kB = (uint32_t)ks * 32u;  // 8 words * 4B
            uint32_t af[4][4], bf[8][2];
            #pragma unroll
            for (int mf = 0; mf < 4; mf++)
                ldsm4(af[mf], aAddr[mf] + aOff + kB);
            #pragma unroll
            for (int f = 0; f < 4; f++) {
                uint32_t t4[4];
                ldsm4(t4, bAddr[f] + bOff + kB);
                bf[2*f  ][0] = t4[0]; bf[2*f+1][0] = t4[1];
                bf[2*f  ][1] = t4[2]; bf[2*f+1][1] = t4[3];
            }
            #pragma unroll
            for (int mf = 0; mf < 4; mf++)
                #pragma unroll
                for (int nf = 0; nf < 8; nf++)
                    mma_fp16(acc[mf][nf], af[mf], bf[nf]);
        }

        if (kc == NKC - 1) {
            // epilogue: mine this 128x256 dot tile
            #pragma unroll
            for (int nf = 0; nf < 8; nf++) {
                const int jl = wc * 64 + nf * 8 + qcol * 2;
                float sqj0 = sqnT[jl],  sqj1 = sqnT[jl + 1];
                int   lj0  = labT[jl],  lj1  = labT[jl + 1];
                #pragma unroll
                for (int mf = 0; mf < 4; mf++)
                    #pragma unroll
                    for (int rh = 0; rh < 2; rh++) {
                        const int irow = i0 + wr * 64 + mf * 16 + qrow + rh * 8;
                        float d20 = fmaxf(fmaf(-2.f, acc[mf][nf][rh * 2 + 0],
                                               sqi[mf][rh] + sqj0), 0.f);
                        float d21 = fmaxf(fmaf(-2.f, acc[mf][nf][rh * 2 + 1],
                                               sqi[mf][rh] + sqj1), 0.f);
                        if (lj0 == li[mf][rh]) {
                            if (j0 + jl != irow)
                                hp2[mf][rh] = fmaxf(hp2[mf][rh], d20);
                        } else hn2[mf][rh] = fminf(hn2[mf][rh], d20);
                        if (lj1 == li[mf][rh]) {
                            if (j0 + jl + 1 != irow)
                                hp2[mf][rh] = fmaxf(hp2[mf][rh], d21);
                        } else hn2[mf][rh] = fminf(hn2[mf][rh], d21);
                    }
            }
        }
        __syncthreads();
    }

    // reduce across the 4 lanes of each quad (same rows, different cols)
    #pragma unroll
    for (int mf = 0; mf < 4; mf++)
        #pragma unroll
        for (int rh = 0; rh < 2; rh++) {
            float hp = hp2[mf][rh], hn = hn2[mf][rh];
            hp = fmaxf(hp, __shfl_xor_sync(0xffffffffu, hp, 1));
            hp = fmaxf(hp, __shfl_xor_sync(0xffffffffu, hp, 2));
            hn = fminf(hn, __shfl_xor_sync(0xffffffffu, hn, 1));
            hn = fminf(hn, __shfl_xor_sync(0xffffffffu, hn, 2));
            if (qcol == 0) {
                int r = i0 + wr * 64 + mf * 16 + qrow + rh * 8;
                atomicMax(&g_hp2[r], __float_as_int(hp));
                atomicMin(&g_hn2[r], __float_as_int(hn));
            }
        }
}

// ---------------------------------------------------------------------------
// Final reduce: per-row loss, masked mean.
// ---------------------------------------------------------------------------
__global__ void reduce_kernel(float* __restrict__ out) {
    __shared__ float ss[1024];
    __shared__ int   sc[1024];
    const int t = threadIdx.x;
    float lsum = 0.f; int lcnt = 0;
    for (int r = t; r < BATCH; r += 1024) {
        int hp = g_hp2[r], hn = g_hn2[r];
        if (hp >= 0 && hn < 0x7f800000) {
            float l = sqrtf(__int_as_float(hp) + 1e-16f)
                    - sqrtf(__int_as_float(hn) + 1e-16f) + MARGIN_F;
            lsum += fmaxf(l, 0.f);
            lcnt += 1;
        }
    }
    ss[t] = lsum; sc[t] = lcnt;
    __syncthreads();
    for (int o = 512; o; o >>= 1) {
        if (t < o) { ss[t] += ss[t + o]; sc[t] += sc[t + o]; }
        __syncthreads();
    }
    if (t == 0) out[0] = ss[0] / fmaxf((float)sc[0], 1.f);
}

extern "C" void kernel_launch(void* const* d_in, const int* in_sizes, int n_in,
                              void* d_out, int out_size) {
    const float* x   = (const float*)d_in[0];
    const int*   lab = (const int*)d_in[1];   // JAX x64-disabled: int32 labels
    float*       out = (float*)d_out;

    cudaFuncSetAttribute(triplet_mma,
                         cudaFuncAttributeMaxDynamicSharedMemorySize, SMEM_BYTES);

    prep_kernel<<<BATCH / 8, 256>>>(x, lab);
    triplet_mma<<<128, 256, SMEM_BYTES>>>();
    reduce_kernel<<<1, 1024>>>(out);
}

// round 7
// speedup vs baseline: 22.1419x; 1.8229x over previous
#include <cuda_runtime.h>
#include <cuda_fp16.h>
#include <cstdint>

#define BATCH    8192
#define DIM      512
#define MARGIN_F 0.3f

#define BM 128                    // i rows per tile (A resident per ib)
#define BN 256                    // j cols per tile
#define BK 64                     // k per B chunk
#define NKC (DIM / BK)            // 8
#define NJT (BATCH / BN)          // 32
#define NIB (BATCH / BM)          // 64
#define NTILES 1056               // sum_{ib<64} (32 - ib/2)

// A: resident 128 rows x 512 halves (+8 pad) = 260 words/row.
// B: staged   256 rows x 64 halves (+8 pad)  = 36 words/row.
// bank start = 4*row mod 32 -> ldmatrix conflict-free.
#define ASTR_W 260
#define BSTR_W 36
#define A_BYTES (BM * ASTR_W * 4)            // 133120
#define B_STAGE_BYTES (BN * BSTR_W * 4)      // 36864
#define OFF_SQNT 0
#define OFF_LABT 1024
#define OFF_A    2048
#define OFF_B    (OFF_A + A_BYTES)           // 135168
#define SMEM_BYTES (OFF_B + 2 * B_STAGE_BYTES)  // 208896

// device scratch
__device__ __half g_xh[BATCH * DIM];     // fp16 embeddings
__device__ float  g_sqn[BATCH];
__device__ int    g_lab[BATCH];
__device__ int    g_hp2[BATCH];          // float bits (d2 >= 0 -> int-monotone)
__device__ int    g_hn2[BATCH];

__device__ __forceinline__ uint32_t smem_u32(const void* p) {
    uint32_t a;
    asm("{ .reg .u64 t; cvta.to.shared.u64 t, %1; cvt.u32.u64 %0, t; }"
        : "=r"(a) : "l"(p));
    return a;
}
__device__ __forceinline__ void cp16(uint32_t saddr, const void* gptr) {
    asm volatile("cp.async.cg.shared.global [%0], [%1], 16;"
                 :: "r"(saddr), "l"(gptr) : "memory");
}
__device__ __forceinline__ void ldsm4(uint32_t* r, uint32_t addr) {
    asm volatile("ldmatrix.sync.aligned.m8n8.x4.shared.b16 {%0,%1,%2,%3}, [%4];"
                 : "=r"(r[0]), "=r"(r[1]), "=r"(r[2]), "=r"(r[3]) : "r"(addr));
}
__device__ __forceinline__ void mma_fp16(float* c, const uint32_t* a,
                                         const uint32_t* b) {
    asm volatile(
        "mma.sync.aligned.m16n8k16.row.col.f32.f16.f16.f32 "
        "{%0,%1,%2,%3}, {%4,%5,%6,%7}, {%8,%9}, {%0,%1,%2,%3};"
        : "+f"(c[0]), "+f"(c[1]), "+f"(c[2]), "+f"(c[3])
        : "r"(a[0]), "r"(a[1]), "r"(a[2]), "r"(a[3]), "r"(b[0]), "r"(b[1]));
}

// ---------------------------------------------------------------------------
// Prep: fp16 conversion, fp32 squared norms, labels, mining-array init.
// ---------------------------------------------------------------------------
__global__ void prep_kernel(const float* __restrict__ x,
                            const int* __restrict__ lab) {
    int row  = blockIdx.x * 8 + (threadIdx.x >> 5);
    int lane = threadIdx.x & 31;
    const float4* xr = reinterpret_cast<const float4*>(x + (size_t)row * DIM);
    float s = 0.f;
    #pragma unroll
    for (int it = 0; it < 4; it++) {
        int c = lane + it * 32;
        float4 v = xr[c];
        s += v.x * v.x + v.y * v.y + v.z * v.z + v.w * v.w;
        __half2 h0 = __floats2half2_rn(v.x, v.y);
        __half2 h1 = __floats2half2_rn(v.z, v.w);
        *reinterpret_cast<__half2*>(&g_xh[row * DIM + c * 4])     = h0;
        *reinterpret_cast<__half2*>(&g_xh[row * DIM + c * 4 + 2]) = h1;
    }
    #pragma unroll
    for (int o = 16; o; o >>= 1) s += __shfl_xor_sync(0xffffffffu, s, o);
    if (lane == 0) {
        g_sqn[row] = s;
        g_lab[row] = lab[row];
        g_hp2[row] = -1;           // sentinel: no positive
        g_hn2[row] = 0x7f800000;   // +inf: no negative
    }
}

// ---------------------------------------------------------------------------
// Main: symmetric fp16 mma.sync Gram + two-sided hard mining.
// Tile set: (ib, jt) with jt >= ib/2 (1056 tiles). Every unordered pair is
// covered at least once; duplicates are idempotent under max/min; self-pairs
// excluded explicitly. Each tile updates both row-side (i) and col-side (j)
// mining via int-bit atomics.
// Static contiguous tile ranges per block (gridDim-adaptive).
// ---------------------------------------------------------------------------
__global__ void __launch_bounds__(256, 1) triplet_sym() {
    extern __shared__ char smem[];
    float* sqnT = reinterpret_cast<float*>(smem + OFF_SQNT);   // 256
    int*   labT = reinterpret_cast<int*>(smem + OFF_LABT);

    const uint32_t sA = smem_u32(smem + OFF_A);
    const uint32_t sB = smem_u32(smem + OFF_B);

    const int tid  = threadIdx.x;
    const int lane = tid & 31;
    const int wid  = tid >> 5;
    const int wr   = wid & 1;        // row half
    const int wc   = wid >> 1;       // col quarter
    const int qrow = lane >> 2;
    const int qcol = lane & 3;
    const int lrow = lane & 15, lksel = lane >> 4;

    // contiguous tile range for this block
    const uint32_t tbeg = (uint32_t)(((uint64_t)blockIdx.x * NTILES) / gridDim.x);
    const uint32_t tend = (uint32_t)(((uint64_t)(blockIdx.x + 1) * NTILES) / gridDim.x);
    if (tbeg >= tend) return;

    // decode tbeg -> (ib, jt);  count(ib) = NJT - ib/2, jt starts at ib/2
    int ib = 0;
    {
        uint32_t rem = tbeg;
        while (rem >= (uint32_t)(NJT - (ib >> 1))) {
            rem -= (uint32_t)(NJT - (ib >> 1));
            ib++;
        }
        // jt set below
        int dummy = 0; (void)dummy;
        // fallthrough with rem
        // (jt initialized after loop)
        // store rem in jt temp:
        ib = ib;  // no-op
        // compute jt
        // NOTE: can't declare jt here cleanly; done outside.
        // We re-derive below.
        // (kept simple: redo decode)
    }
    int jt;
    {
        uint32_t rem = tbeg;
        int b = 0;
        while (rem >= (uint32_t)(NJT - (b >> 1))) {
            rem -= (uint32_t)(NJT - (b >> 1));
            b++;
        }
        ib = b;
        jt = (b >> 1) + (int)rem;
    }

    uint32_t bAddr[4];
    #pragma unroll
    for (int f = 0; f < 4; f++)
        bAddr[f] = sB + ((wc * 64 + f * 16 + lrow) * BSTR_W + 4 * lksel) * 4;

    int cur_ib = -1, i0 = 0;
    float sqi[4][2];
    int   li [4][2];
    uint32_t aAddr[4];
    float acc[4][8][4];

    auto load_B = [&](int j0_, int kc_, int s_) {
        const int k0 = kc_ * BK;
        const uint32_t bbase = sB + (uint32_t)s_ * B_STAGE_BYTES;
        #pragma unroll
        for (int it = 0; it < 8; it++) {
            int seg = tid + it * 256;
            int n = seg >> 3, sc = seg & 7;
            cp16(bbase + (n * BSTR_W + sc * 4) * 4,
                 g_xh + (j0_ + n) * DIM + k0 + sc * 8);
        }
        asm volatile("cp.async.commit_group;" ::: "memory");
    };

    for (uint32_t t = tbeg; t < tend; t++) {
        const int j0 = jt * BN;

        if (ib != cur_ib) {
            // previous tile's mma/ldsm done (trailing __syncthreads); safe to
            // overwrite A. Committed as its own cp.async group BEFORE B0.
            cur_ib = ib;
            i0 = ib * BM;
            #pragma unroll
            for (int it = 0; it < 32; it++) {
                int seg = tid + it * 256;
                int m = seg >> 6, sc = seg & 63;
                cp16(sA + (m * ASTR_W + sc * 4) * 4,
                     g_xh + (i0 + m) * DIM + sc * 8);
            }
            asm volatile("cp.async.commit_group;" ::: "memory");
            #pragma unroll
            for (int mf = 0; mf < 4; mf++)
                #pragma unroll
                for (int rh = 0; rh < 2; rh++) {
                    int r = i0 + wr * 64 + mf * 16 + qrow + rh * 8;
                    sqi[mf][rh] = g_sqn[r];
                    li [mf][rh] = g_lab[r];
                }
            #pragma unroll
            for (int mf = 0; mf < 4; mf++)
                aAddr[mf] = sA + ((wr * 64 + mf * 16 + lrow) * ASTR_W
                                  + 4 * lksel) * 4;
        }

        load_B(j0, 0, 0);

        for (int kc = 0; kc < NKC; kc++) {
            if (kc + 1 < NKC) {
                load_B(j0, kc + 1, (kc + 1) & 1);
                asm volatile("cp.async.wait_group 1;" ::: "memory");
            } else {
                asm volatile("cp.async.wait_group 0;" ::: "memory");
            }
            if (kc == 0) {
                sqnT[tid] = g_sqn[j0 + tid];    // prev epilogue readers done
                labT[tid] = g_lab[j0 + tid];    // (trailing sync of prev tile)
            }
            __syncthreads();

            if (kc == 0) {
                #pragma unroll
                for (int mf = 0; mf < 4; mf++)
                    #pragma unroll
                    for (int nf = 0; nf < 8; nf++)
                        #pragma unroll
                        for (int q = 0; q < 4; q++) acc[mf][nf][q] = 0.f;
            }

            const uint32_t aOff = (uint32_t)kc * 128u;    // kc*32 words *4B
            const uint32_t bOff = (uint32_t)(kc & 1) * B_STAGE_BYTES;

            #pragma unroll
            for (int ks = 0; ks < 4; ks++) {              // 4 x k16 = BK
                const uint32_t kB = (uint32_t)ks * 32u;
                uint32_t af[4][4], bf[8][2];
                #pragma unroll
                for (int mf = 0; mf < 4; mf++)
                    ldsm4(af[mf], aAddr[mf] + aOff + kB);
                #pragma unroll
                for (int f = 0; f < 4; f++) {
                    uint32_t t4[4];
                    ldsm4(t4, bAddr[f] + bOff + kB);
                    bf[2*f  ][0] = t4[0]; bf[2*f+1][0] = t4[1];
                    bf[2*f  ][1] = t4[2]; bf[2*f+1][1] = t4[3];
                }
                #pragma unroll
                for (int mf = 0; mf < 4; mf++)
                    #pragma unroll
                    for (int nf = 0; nf < 8; nf++)
                        mma_fp16(acc[mf][nf], af[mf], bf[nf]);
            }

            if (kc == NKC - 1) {
                // ---- two-sided mining epilogue ----
                const float INF = __int_as_float(0x7f800000);
                float hpr[4][2], hnr[4][2];
                #pragma unroll
                for (int mf = 0; mf < 4; mf++)
                    #pragma unroll
                    for (int rh = 0; rh < 2; rh++) {
                        hpr[mf][rh] = -1.0f; hnr[mf][rh] = INF;
                    }
                #pragma unroll
                for (int nf = 0; nf < 8; nf++) {
                    const int jl  = wc * 64 + nf * 8 + qcol * 2;
                    const int jg0 = j0 + jl, jg1 = jg0 + 1;
                    const float sqj0 = sqnT[jl], sqj1 = sqnT[jl + 1];
                    const int   lj0  = labT[jl], lj1  = labT[jl + 1];
                    float hpc0 = -1.f, hnc0 = INF, hpc1 = -1.f, hnc1 = INF;
                    #pragma unroll
                    for (int mf = 0; mf < 4; mf++)
                        #pragma unroll
                        for (int rh = 0; rh < 2; rh++) {
                            const int irow = i0 + wr * 64 + mf * 16
                                             + qrow + rh * 8;
                            float d20 = fmaxf(fmaf(-2.f, acc[mf][nf][rh*2+0],
                                                   sqi[mf][rh] + sqj0), 0.f);
                            float d21 = fmaxf(fmaf(-2.f, acc[mf][nf][rh*2+1],
                                                   sqi[mf][rh] + sqj1), 0.f);
                            if (lj0 == li[mf][rh]) {
                                if (jg0 != irow) {
                                    hpr[mf][rh] = fmaxf(hpr[mf][rh], d20);
                                    hpc0 = fmaxf(hpc0, d20);
                                }
                            } else {
                                hnr[mf][rh] = fminf(hnr[mf][rh], d20);
                                hnc0 = fminf(hnc0, d20);
                            }
                            if (lj1 == li[mf][rh]) {
                                if (jg1 != irow) {
                                    hpr[mf][rh] = fmaxf(hpr[mf][rh], d21);
                                    hpc1 = fmaxf(hpc1, d21);
                                }
                            } else {
                                hnr[mf][rh] = fminf(hnr[mf][rh], d21);
                                hnc1 = fminf(hnc1, d21);
                            }
                        }
                    // column-side reduce across qrow lanes
                    #pragma unroll
                    for (int off = 4; off <= 16; off <<= 1) {
                        hpc0 = fmaxf(hpc0, __shfl_xor_sync(0xffffffffu, hpc0, off));
                        hnc0 = fminf(hnc0, __shfl_xor_sync(0xffffffffu, hnc0, off));
                        hpc1 = fmaxf(hpc1, __shfl_xor_sync(0xffffffffu, hpc1, off));
                        hnc1 = fminf(hnc1, __shfl_xor_sync(0xffffffffu, hnc1, off));
                    }
                    if (qrow == 0) {
                        atomicMax(&g_hp2[jg0], __float_as_int(hpc0));
                        atomicMin(&g_hn2[jg0], __float_as_int(hnc0));
                        atomicMax(&g_hp2[jg1], __float_as_int(hpc1));
                        atomicMin(&g_hn2[jg1], __float_as_int(hnc1));
                    }
                }
                // row-side reduce across qcol lanes
                #pragma unroll
                for (int mf = 0; mf < 4; mf++)
                    #pragma unroll
                    for (int rh = 0; rh < 2; rh++) {
                        float hp = hpr[mf][rh], hn = hnr[mf][rh];
                        hp = fmaxf(hp, __shfl_xor_sync(0xffffffffu, hp, 1));
                        hp = fmaxf(hp, __shfl_xor_sync(0xffffffffu, hp, 2));
                        hn = fminf(hn, __shfl_xor_sync(0xffffffffu, hn, 1));
                        hn = fminf(hn, __shfl_xor_sync(0xffffffffu, hn, 2));
                        if (qcol == 0) {
                            int r = i0 + wr * 64 + mf * 16 + qrow + rh * 8;
                            atomicMax(&g_hp2[r], __float_as_int(hp));
                            atomicMin(&g_hn2[r], __float_as_int(hn));
                        }
                    }
            }
            __syncthreads();
        }

        // advance to next tile (ib-major order keeps A resident)
        jt++;
        if (jt == NJT) { ib++; jt = ib >> 1; }
    }
}

// ---------------------------------------------------------------------------
// Final reduce: per-row loss, masked mean.
// ---------------------------------------------------------------------------
__global__ void reduce_kernel(float* __restrict__ out) {
    __shared__ float ss[1024];
    __shared__ int   sc[1024];
    const int t = threadIdx.x;
    float lsum = 0.f; int lcnt = 0;
    for (int r = t; r < BATCH; r += 1024) {
        int hp = g_hp2[r], hn = g_hn2[r];
        if (hp >= 0 && hn < 0x7f800000) {
            float l = sqrtf(__int_as_float(hp) + 1e-16f)
                    - sqrtf(__int_as_float(hn) + 1e-16f) + MARGIN_F;
            lsum += fmaxf(l, 0.f);
            lcnt += 1;
        }
    }
    ss[t] = lsum; sc[t] = lcnt;
    __syncthreads();
    for (int o = 512; o; o >>= 1) {
        if (t < o) { ss[t] += ss[t + o]; sc[t] += sc[t + o]; }
        __syncthreads();
    }
    if (t == 0) out[0] = ss[0] / fmaxf((float)sc[0], 1.f);
}

extern "C" void kernel_launch(void* const* d_in, const int* in_sizes, int n_in,
                              void* d_out, int out_size) {
    const float* x   = (const float*)d_in[0];
    const int*   lab = (const int*)d_in[1];   // JAX x64-disabled: int32 labels
    float*       out = (float*)d_out;

    static int nsm = 0;
    if (nsm == 0) {
        int dev = 0;
        cudaGetDevice(&dev);
        if (cudaDeviceGetAttribute(&nsm, cudaDevAttrMultiProcessorCount, dev)
            != cudaSuccess || nsm < 1 || nsm > NTILES)
            nsm = 148;
    }

    cudaFuncSetAttribute(triplet_sym,
                         cudaFuncAttributeMaxDynamicSharedMemorySize, SMEM_BYTES);

    prep_kernel<<<BATCH / 8, 256>>>(x, lab);
    triplet_sym<<<nsm, 256, SMEM_BYTES>>>();
    reduce_kernel<<<1, 1024>>>(out);
}